// round 15
// baseline (speedup 1.0000x reference)
#include <cuda_runtime.h>
#include <cuda_bf16.h>
#include <cstdint>

#define HID  200
#define DD   8
#define SB   8            // samples per block
#define NG   100          // column groups (100 * 2 = 200 cols)
#define NCOL 2            // columns per thread
#define NTH  416          // 13 warps; 400 active (100 groups x 4 sample-pairs)
#define NW   13
#define SPS  20           // floats per sample-pair record (18 used: 8 dirs x2 + primal x2)
#define PADK 84           // floats per k row: 4*SPS=80 +4 pad
#define EPSV 0.1f
#define DSMEM (HID * PADK * 4)   // 67200 bytes dynamic

// Pre-transposed weights (device scratch; no allocation)
__device__ float g_W1T[HID * HID];
__device__ float g_W2T[HID * HID];

__global__ void transposeW(const float* __restrict__ W1, const float* __restrict__ W2) {
    int idx = blockIdx.x * blockDim.x + threadIdx.x;
    if (idx < HID * HID) {
        int r = idx / HID, c = idx % HID;
        g_W1T[c * HID + r] = W1[idx];
        g_W2T[c * HID + r] = W2[idx];
    }
}

typedef unsigned long long u64;
typedef unsigned int u32;

__device__ __forceinline__ u64 pack2(float lo, float hi) {
    u64 r; asm("mov.b64 %0, {%1, %2};" : "=l"(r) : "f"(lo), "f"(hi)); return r;
}
__device__ __forceinline__ float2 unpack2(u64 v) {
    float2 r; asm("mov.b64 {%0, %1}, %2;" : "=f"(r.x), "=f"(r.y) : "l"(v)); return r;
}
__device__ __forceinline__ u64 fma2(u64 a, u64 b, u64 c) {
    u64 d; asm("fma.rn.f32x2 %0, %1, %2, %3;" : "=l"(d) : "l"(a), "l"(b), "l"(c)); return d;
}

__device__ __forceinline__ float sigm(float x)     { return 1.0f / (1.0f + expf(-x)); }
__device__ __forceinline__ float softplusf(float x){ return fmaxf(x, 0.0f) + log1pf(expf(-fabsf(x))); }

__device__ __forceinline__ u32 bfpack(float a, float b) {
    __nv_bfloat162 p = __floats2bfloat162_rn(a, b);
    return *reinterpret_cast<u32*>(&p);
}
__device__ __forceinline__ float2 bfunpack(u32 v) {
    return __bfloat1622float2(*reinterpret_cast<__nv_bfloat162*>(&v));
}

// One k-step: C[r][c] += Apair_r * (w_c, w_c).
// A pairs (s0,s1) straight from LDS (zero packs); W from buffer slot B (2 packs).
// 18 FFMA2 + 5 LDS + 2 packs.
#define GEMM_STEP_B(kk, B)                                                      \
    {                                                                           \
        const float* ap = &db[(kk) * PADK + sp * SPS];                          \
        ulonglong2 A01 = *reinterpret_cast<const ulonglong2*>(ap);              \
        ulonglong2 A23 = *reinterpret_cast<const ulonglong2*>(ap + 4);          \
        ulonglong2 A45 = *reinterpret_cast<const ulonglong2*>(ap + 8);          \
        ulonglong2 A67 = *reinterpret_cast<const ulonglong2*>(ap + 12);         \
        u64 A8 = *reinterpret_cast<const u64*>(ap + 16);                        \
        u64 av[9] = {A01.x, A01.y, A23.x, A23.y, A45.x, A45.y, A67.x, A67.y, A8}; \
        u64 uw0 = pack2(wb[B].x, wb[B].x), uw1 = pack2(wb[B].y, wb[B].y);       \
        _Pragma("unroll")                                                       \
        for (int r = 0; r < 9; r++) {                                           \
            Cp[r][0] = fma2(av[r], uw0, Cp[r][0]);                              \
            Cp[r][1] = fma2(av[r], uw1, Cp[r][1]);                              \
        }                                                                       \
    }

// Full phase: W double-buffered in registers (MOV-free alternation).
#define GEMM_PHASE(Wb)                                                          \
    {                                                                           \
        _Pragma("unroll")                                                       \
        for (int r = 0; r < 9; r++) { Cp[r][0] = 0ull; Cp[r][1] = 0ull; }       \
        const float* wp = &(Wb)[col0];                                          \
        float2 wb[2];                                                           \
        wb[0] = *reinterpret_cast<const float2*>(wp);                           \
        for (int k = 0; k < HID - 2; k += 2) {                                  \
            wb[1] = *reinterpret_cast<const float2*>(wp + HID);                 \
            GEMM_STEP_B(k, 0);                                                  \
            wp += 2 * HID;                                                      \
            wb[0] = *reinterpret_cast<const float2*>(wp);                       \
            GEMM_STEP_B(k + 1, 1);                                              \
        }                                                                       \
        wb[1] = *reinterpret_cast<const float2*>(wp + HID);                     \
        GEMM_STEP_B(HID - 2, 0);                                                \
        GEMM_STEP_B(HID - 1, 1);                                                \
    }

__global__ void __launch_bounds__(NTH, 2) lnn_kernel(
    const float* __restrict__ z,
    const float* __restrict__ W0, const float* __restrict__ b0,
    const float* __restrict__ W1, const float* __restrict__ b1,
    const float* __restrict__ W2, const float* __restrict__ b2,
    const float* __restrict__ W3,
    float* __restrict__ out, int n)
{
    extern __shared__ float db[];              // [HID][PADK], sample-interleaved dirs
    __shared__ uint4 th2b[HID][SB];            // bf16-packed th2 per (col, sample)
    __shared__ float shz[SB][16];
    __shared__ float sh_g[SB][16];
    __shared__ float sh_H[SB][8][16];

    const int tid  = threadIdx.x;
    const int sp   = tid & 3;              // sample pair 0..3
    const int g    = tid >> 2;             // column group
    const int col0 = g * NCOL;
    const bool act = (g < NG);
    const int s0   = 2 * sp, s1v = 2 * sp + 1;
    const int base = blockIdx.x * SB;
    const int warp = tid >> 5, lane = tid & 31;

    for (int i = tid; i < SB * 16; i += NTH) {
        int smp = base + (i >> 4);
        if (smp >= n) smp = n - 1;
        shz[i >> 4][i & 15] = z[smp * 16 + (i & 15)];
    }
    __syncthreads();

    float s1r[2][NCOL], s2r[2][NCOL];
    u64 Cp[9][2];

    // ---------- phase 0: x1 = z@W0 + b0 ; seed tangents ----------
    if (act) {
        float xa0[NCOL], xa1[NCOL];
        float2 bb = *reinterpret_cast<const float2*>(&b0[col0]);
        xa0[0] = bb.x; xa0[1] = bb.y; xa1[0] = bb.x; xa1[1] = bb.y;
        #pragma unroll
        for (int m = 0; m < 16; m++) {
            float2 wv = *reinterpret_cast<const float2*>(&W0[m * HID + col0]);
            float z0 = shz[s0][m], z1 = shz[s1v][m];
            xa0[0] = fmaf(z0, wv.x, xa0[0]); xa0[1] = fmaf(z0, wv.y, xa0[1]);
            xa1[0] = fmaf(z1, wv.x, xa1[0]); xa1[1] = fmaf(z1, wv.y, xa1[1]);
        }
        #pragma unroll
        for (int c = 0; c < NCOL; c++) {
            s1r[0][c] = sigm(xa0[c]);
            s1r[1][c] = sigm(xa1[c]);
            *reinterpret_cast<u64*>(&db[(col0 + c) * PADK + sp * SPS + 16]) =
                pack2(softplusf(xa0[c]), softplusf(xa1[c]));
        }
        #pragma unroll
        for (int d = 0; d < DD; d++) {
            float2 wv = *reinterpret_cast<const float2*>(&W0[(DD + d) * HID + col0]);
            *reinterpret_cast<u64*>(&db[col0 * PADK + sp * SPS + 2 * d]) =
                pack2(s1r[0][0] * wv.x, s1r[1][0] * wv.x);
            *reinterpret_cast<u64*>(&db[(col0 + 1) * PADK + sp * SPS + 2 * d]) =
                pack2(s1r[0][1] * wv.y, s1r[1][1] * wv.y);
        }
    }
    __syncthreads();

    // ---------- phase 1: stream W1 -> x2 + t2 ----------
    if (act) { GEMM_PHASE(W1); }
    __syncthreads();
    if (act) {
        float2 bb = *reinterpret_cast<const float2*>(&b1[col0]);
        float bw[NCOL] = {bb.x, bb.y};
        #pragma unroll
        for (int c = 0; c < NCOL; c++) {
            float2 xp = unpack2(Cp[8][c]);
            float x0 = xp.x + bw[c], x1 = xp.y + bw[c];
            float sA = sigm(x0), sB = sigm(x1);
            s2r[0][c] = sA; s2r[1][c] = sB;
            float v0[DD], v1[DD];
            #pragma unroll
            for (int d = 0; d < DD; d++) {
                float2 t = unpack2(Cp[d][c]);
                v0[d] = sA * t.x; v1[d] = sB * t.y;       // th2 = s2*t2
            }
            float* p = &db[(col0 + c) * PADK + sp * SPS];
            *reinterpret_cast<float4*>(p)      = make_float4(v0[0], v1[0], v0[1], v1[1]);
            *reinterpret_cast<float4*>(p + 4)  = make_float4(v0[2], v1[2], v0[3], v1[3]);
            *reinterpret_cast<float4*>(p + 8)  = make_float4(v0[4], v1[4], v0[5], v1[5]);
            *reinterpret_cast<float4*>(p + 12) = make_float4(v0[6], v1[6], v0[7], v1[7]);
            *reinterpret_cast<u64*>(p + 16)    = pack2(softplusf(x0), softplusf(x1));   // h2
            uint4 t0, t1;
            t0.x = bfpack(v0[0], v0[1]); t0.y = bfpack(v0[2], v0[3]);
            t0.z = bfpack(v0[4], v0[5]); t0.w = bfpack(v0[6], v0[7]);
            t1.x = bfpack(v1[0], v1[1]); t1.y = bfpack(v1[2], v1[3]);
            t1.z = bfpack(v1[4], v1[5]); t1.w = bfpack(v1[6], v1[7]);
            th2b[col0 + c][s0]  = t0;
            th2b[col0 + c][s1v] = t1;
        }
    }
    __syncthreads();

    // ---------- phase 2: stream W2 -> x3 + t3 ----------
    if (act) { GEMM_PHASE(W2); }
    __syncthreads();
    if (act) {
        float2 bb = *reinterpret_cast<const float2*>(&b2[col0]);
        float2 w3 = *reinterpret_cast<const float2*>(&W3[col0]);
        float bw[NCOL] = {bb.x, bb.y};
        float w3v[NCOL] = {w3.x, w3.y};
        #pragma unroll
        for (int c = 0; c < NCOL; c++) {
            float2 xp = unpack2(Cp[8][c]);
            float x0 = xp.x + bw[c], x1 = xp.y + bw[c];
            float sA = sigm(x0), sB = sigm(x1);
            float cA = w3v[c] * sA * (1.0f - sA);
            float cB = w3v[c] * sB * (1.0f - sB);
            float v0[DD], v1[DD];
            #pragma unroll
            for (int d = 0; d < DD; d++) {
                float2 t = unpack2(Cp[d][c]);
                v0[d] = cA * t.x; v1[d] = cB * t.y;       // delta-d3
            }
            float* p = &db[(col0 + c) * PADK + sp * SPS];
            *reinterpret_cast<float4*>(p)      = make_float4(v0[0], v1[0], v0[1], v1[1]);
            *reinterpret_cast<float4*>(p + 4)  = make_float4(v0[2], v1[2], v0[3], v1[3]);
            *reinterpret_cast<float4*>(p + 8)  = make_float4(v0[4], v1[4], v0[5], v1[5]);
            *reinterpret_cast<float4*>(p + 12) = make_float4(v0[6], v1[6], v0[7], v1[7]);
            *reinterpret_cast<u64*>(p + 16)    = pack2(w3v[c] * sA, w3v[c] * sB);      // d3
        }
    }
    __syncthreads();

    // ---------- phase 3: stream W2^T -> u2 + r2 ----------
    if (act) { GEMM_PHASE(g_W2T); }
    __syncthreads();
    if (act) {
        #pragma unroll
        for (int c = 0; c < NCOL; c++) {
            float2 up = unpack2(Cp[8][c]);     // u2 (s0, s1)
            float sA = s2r[0][c], sB = s2r[1][c];
            float kA = (1.0f - sA) * up.x, kB = (1.0f - sB) * up.y;
            uint4 t0v = th2b[col0 + c][s0];
            uint4 t1v = th2b[col0 + c][s1v];
            float tA[DD], tB[DD];
            { float2 p2;
              p2 = bfunpack(t0v.x); tA[0] = p2.x; tA[1] = p2.y;
              p2 = bfunpack(t0v.y); tA[2] = p2.x; tA[3] = p2.y;
              p2 = bfunpack(t0v.z); tA[4] = p2.x; tA[5] = p2.y;
              p2 = bfunpack(t0v.w); tA[6] = p2.x; tA[7] = p2.y;
              p2 = bfunpack(t1v.x); tB[0] = p2.x; tB[1] = p2.y;
              p2 = bfunpack(t1v.y); tB[2] = p2.x; tB[3] = p2.y;
              p2 = bfunpack(t1v.z); tB[4] = p2.x; tB[5] = p2.y;
              p2 = bfunpack(t1v.w); tB[6] = p2.x; tB[7] = p2.y; }
            float v0[DD], v1[DD];
            #pragma unroll
            for (int d = 0; d < DD; d++) {
                float2 r = unpack2(Cp[d][c]);
                v0[d] = fmaf(sA, r.x, kA * tA[d]);        // delta-d2
                v1[d] = fmaf(sB, r.y, kB * tB[d]);
            }
            float* p = &db[(col0 + c) * PADK + sp * SPS];
            *reinterpret_cast<float4*>(p)      = make_float4(v0[0], v1[0], v0[1], v1[1]);
            *reinterpret_cast<float4*>(p + 4)  = make_float4(v0[2], v1[2], v0[3], v1[3]);
            *reinterpret_cast<float4*>(p + 8)  = make_float4(v0[4], v1[4], v0[5], v1[5]);
            *reinterpret_cast<float4*>(p + 12) = make_float4(v0[6], v1[6], v0[7], v1[7]);
            *reinterpret_cast<u64*>(p + 16)    = pack2(sA * up.x, sB * up.y);          // d2
        }
    }
    __syncthreads();

    // ---------- phase 4: stream W1^T -> u1 + r1 ----------
    if (act) { GEMM_PHASE(g_W1T); }
    __syncthreads();
    if (act) {
        float coA[NCOL], coB[NCOL];
        #pragma unroll
        for (int c = 0; c < NCOL; c++) {
            float2 up = unpack2(Cp[8][c]);     // u1
            coA[c] = s1r[0][c] * (1.0f - s1r[0][c]) * up.x;
            coB[c] = s1r[1][c] * (1.0f - s1r[1][c]) * up.y;
            *reinterpret_cast<u64*>(&db[(col0 + c) * PADK + sp * SPS + 16]) =
                pack2(s1r[0][c] * up.x, s1r[1][c] * up.y);   // d1
        }
        #pragma unroll
        for (int d = 0; d < DD; d++) {
            float2 wv = *reinterpret_cast<const float2*>(&W0[(DD + d) * HID + col0]);
            float wvv[NCOL] = {wv.x, wv.y};
            #pragma unroll
            for (int c = 0; c < NCOL; c++) {
                float2 r = unpack2(Cp[d][c]);
                *reinterpret_cast<u64*>(&db[(col0 + c) * PADK + sp * SPS + 2 * d]) =
                    pack2(fmaf(s1r[0][c], r.x, coA[c] * wvv[c]),
                          fmaf(s1r[1][c], r.y, coB[c] * wvv[c]));   // delta-d1
            }
        }
    }
    __syncthreads();

    // ---------- final dots ----------
    for (int idx = warp; idx < SB * 16; idx += NW) {
        int ss = idx >> 4, m = idx & 15;
        float a = 0.0f;
        for (int k = lane; k < HID; k += 32)
            a = fmaf(W0[m * HID + k], db[k * PADK + (ss >> 1) * SPS + 16 + (ss & 1)], a);
        #pragma unroll
        for (int off = 16; off > 0; off >>= 1) a += __shfl_xor_sync(0xffffffffu, a, off);
        if (lane == 0) sh_g[ss][m] = a;
    }
    for (int idx = warp; idx < SB * 128; idx += NW) {
        int ss = idx >> 7;
        int r = idx & 127;
        int d = r >> 4, m = r & 15;
        float a = 0.0f;
        for (int k = lane; k < HID; k += 32)
            a = fmaf(W0[m * HID + k], db[k * PADK + (ss >> 1) * SPS + 2 * d + (ss & 1)], a);
        #pragma unroll
        for (int off = 16; off > 0; off >>= 1) a += __shfl_xor_sync(0xffffffffu, a, off);
        if (lane == 0) sh_H[ss][d][m] = a;
    }
    __syncthreads();

    // ---------- per-sample 8x8 solve + output ----------
    if (tid < SB && base + tid < n) {
        const int ss = tid;
        float Mt[DD][DD], Fv[DD], av2[DD], vv[DD];
        #pragma unroll
        for (int c = 0; c < DD; c++) vv[c] = shz[ss][DD + c];
        for (int r = 0; r < DD; r++)
            for (int c = 0; c < DD; c++)
                Mt[r][c] = sh_H[ss][r][DD + c] + ((r == c) ? 2.0f * EPSV : 0.0f);
        for (int p = 0; p < DD; p++) {
            float f = sh_g[ss][p];
            for (int c = 0; c < DD; c++) f -= sh_H[ss][p][c] * vv[c];
            Fv[p] = f;
        }
        for (int col = 0; col < DD; col++) {
            int piv = col; float best = fabsf(Mt[col][col]);
            for (int r = col + 1; r < DD; r++) {
                float m = fabsf(Mt[r][col]);
                if (m > best) { best = m; piv = r; }
            }
            if (piv != col) {
                for (int c = col; c < DD; c++) { float t = Mt[col][c]; Mt[col][c] = Mt[piv][c]; Mt[piv][c] = t; }
                float t = Fv[col]; Fv[col] = Fv[piv]; Fv[piv] = t;
            }
            float inv = 1.0f / Mt[col][col];
            for (int r = col + 1; r < DD; r++) {
                float fac = Mt[r][col] * inv;
                for (int c = col; c < DD; c++) Mt[r][c] -= fac * Mt[col][c];
                Fv[r] -= fac * Fv[col];
            }
        }
        for (int r = DD - 1; r >= 0; r--) {
            float x = Fv[r];
            for (int c = r + 1; c < DD; c++) x -= Mt[r][c] * av2[c];
            av2[r] = x / Mt[r][r];
        }
        const int gi = (base + ss) * 16;
        #pragma unroll
        for (int j = 0; j < DD; j++) out[gi + j] = vv[j];
        #pragma unroll
        for (int j = 0; j < DD; j++) out[gi + DD + j] = av2[j];
    }
}

extern "C" void kernel_launch(void* const* d_in, const int* in_sizes, int n_in,
                              void* d_out, int out_size) {
    const float* z  = (const float*)d_in[1];
    const float* W0 = (const float*)d_in[2];
    const float* b0 = (const float*)d_in[3];
    const float* W1 = (const float*)d_in[4];
    const float* b1 = (const float*)d_in[5];
    const float* W2 = (const float*)d_in[6];
    const float* b2 = (const float*)d_in[7];
    const float* W3 = (const float*)d_in[8];
    float* out = (float*)d_out;

    const int n = in_sizes[1] / 16;

    cudaFuncSetAttribute(lnn_kernel, cudaFuncAttributeMaxDynamicSharedMemorySize, DSMEM);

    transposeW<<<(HID * HID + 255) / 256, 256>>>(W1, W2);

    const int blocks = (n + SB - 1) / SB;
    lnn_kernel<<<blocks, NTH, DSMEM>>>(z, W0, b0, W1, b1, W2, b2, W3, out, n);
}

// round 16
// speedup vs baseline: 1.2548x; 1.2548x over previous
#include <cuda_runtime.h>
#include <cuda_bf16.h>
#include <cstdint>

#define HID  200
#define DD   8
#define SB   8            // samples per block
#define MM   80           // GEMM M: 8 samples * 10 rows (9 used + 1 pad)
#define RS   204          // smem row stride (floats): conflict-free A-frag reads
#define NTH  800          // 25 warps: warp = (mi 0..4) x (ni 0..4)
#define NWARP 25
#define EPSV 0.1f
#define DSMEM (2 * MM * RS * 4)   // Abuf + Cbuf = 130560 B

typedef unsigned int u32;
typedef unsigned long long u64;

// tf32 split planes of the 4 phase matrices: [0]=W1, [1]=W2, [2]=W2^T, [3]=W1^T
__device__ float g_Bh[4][HID * HID];
__device__ float g_Bl[4][HID * HID];

__device__ __forceinline__ u32 tf32r(float x) {
    u32 r; asm("cvt.rna.tf32.f32 %0, %1;" : "=r"(r) : "f"(x)); return r;
}

__global__ void prepW(const float* __restrict__ W1, const float* __restrict__ W2) {
    int idx = blockIdx.x * blockDim.x + threadIdx.x;
    if (idx >= HID * HID) return;
    int r = idx / HID, c = idx % HID;
    float w1 = W1[idx], w2 = W2[idx];
    u32 h1 = tf32r(w1); float h1f = __uint_as_float(h1);
    u32 l1 = tf32r(w1 - h1f);
    u32 h2 = tf32r(w2); float h2f = __uint_as_float(h2);
    u32 l2 = tf32r(w2 - h2f);
    g_Bh[0][idx] = h1f;  g_Bl[0][idx] = __uint_as_float(l1);
    g_Bh[1][idx] = h2f;  g_Bl[1][idx] = __uint_as_float(l2);
    int tidx = c * HID + r;
    g_Bh[2][tidx] = h2f; g_Bl[2][tidx] = __uint_as_float(l2);
    g_Bh[3][tidx] = h1f; g_Bl[3][tidx] = __uint_as_float(l1);
}

__device__ __forceinline__ float sigm(float x)     { return 1.0f / (1.0f + expf(-x)); }
__device__ __forceinline__ float softplusf(float x){ return fmaxf(x, 0.0f) + log1pf(expf(-fabsf(x))); }

__device__ __forceinline__ u32 bfpack(float a, float b) {
    __nv_bfloat162 p = __floats2bfloat162_rn(a, b);
    return *reinterpret_cast<u32*>(&p);
}
__device__ __forceinline__ float2 bfunpack(u32 v) {
    return __bfloat1622float2(*reinterpret_cast<__nv_bfloat162*>(&v));
}

__device__ __forceinline__ void mma8(float& c0, float& c1, float& c2, float& c3,
                                     u32 a0, u32 a1, u32 a2, u32 a3, u32 b0, u32 b1) {
    asm volatile(
        "mma.sync.aligned.m16n8k8.row.col.f32.tf32.tf32.f32 "
        "{%0,%1,%2,%3},{%4,%5,%6,%7},{%8,%9},{%0,%1,%2,%3};"
        : "+f"(c0), "+f"(c1), "+f"(c2), "+f"(c3)
        : "r"(a0), "r"(a1), "r"(a2), "r"(a3), "r"(b0), "r"(b1));
}

// One phase: Cb[80x200] = Ab[80x200] @ B_p[200x200], 3xTF32 split.
// All 25 warps participate; warp (mi,ni) owns rows [16mi,16mi+16) x cols [40ni,40ni+40).
__device__ __forceinline__ void gemm_phase(int p, const float* Ab, float* Cb,
                                           int mi, int ni, int lane) {
    float C[5][4];
    #pragma unroll
    for (int t = 0; t < 5; t++) { C[t][0] = 0; C[t][1] = 0; C[t][2] = 0; C[t][3] = 0; }
    const float* ap = Ab + (mi * 16 + (lane >> 2)) * RS + (lane & 3);
    const u32* bh = reinterpret_cast<const u32*>(g_Bh[p]) + (lane & 3) * HID + ni * 40 + (lane >> 2);
    const u32* bl = reinterpret_cast<const u32*>(g_Bl[p]) + (lane & 3) * HID + ni * 40 + (lane >> 2);
    for (int k0 = 0; k0 < HID; k0 += 8) {
        float a0 = ap[0], a2 = ap[4], a1 = ap[8 * RS], a3 = ap[8 * RS + 4];
        u32 ah0 = tf32r(a0), ah1 = tf32r(a1), ah2 = tf32r(a2), ah3 = tf32r(a3);
        u32 al0 = tf32r(a0 - __uint_as_float(ah0));
        u32 al1 = tf32r(a1 - __uint_as_float(ah1));
        u32 al2 = tf32r(a2 - __uint_as_float(ah2));
        u32 al3 = tf32r(a3 - __uint_as_float(ah3));
        #pragma unroll
        for (int t = 0; t < 5; t++) {
            u32 h0 = bh[t * 8], h1 = bh[t * 8 + 4 * HID];
            u32 l0 = bl[t * 8], l1 = bl[t * 8 + 4 * HID];
            mma8(C[t][0], C[t][1], C[t][2], C[t][3], ah0, ah1, ah2, ah3, h0, h1);
            mma8(C[t][0], C[t][1], C[t][2], C[t][3], ah0, ah1, ah2, ah3, l0, l1);
            mma8(C[t][0], C[t][1], C[t][2], C[t][3], al0, al1, al2, al3, h0, h1);
        }
        ap += 8; bh += 8 * HID; bl += 8 * HID;
    }
    float* cp = Cb + (mi * 16 + (lane >> 2)) * RS + ni * 40 + (lane & 3) * 2;
    #pragma unroll
    for (int t = 0; t < 5; t++) {
        *reinterpret_cast<float2*>(cp + t * 8)          = make_float2(C[t][0], C[t][1]);
        *reinterpret_cast<float2*>(cp + t * 8 + 8 * RS) = make_float2(C[t][2], C[t][3]);
    }
}

__global__ void __launch_bounds__(NTH, 1) lnn_kernel(
    const float* __restrict__ z,
    const float* __restrict__ W0, const float* __restrict__ b0,
    const float* __restrict__ b1, const float* __restrict__ b2,
    const float* __restrict__ W3,
    float* __restrict__ out, int n)
{
    extern __shared__ float sm[];
    float* Ab = sm;                 // [80][204] operand rows: row = s*10 + d (d=8 primal, d=9 pad)
    float* Cb = sm + MM * RS;       // [80][204] GEMM output
    __shared__ u32 th2b[HID][SB][4];   // bf16-packed th2 (8 dirs) per (col, sample)
    __shared__ float shz[SB][16];
    __shared__ float sh_g[SB][16];
    __shared__ float sh_H[SB][8][16];

    const int tid  = threadIdx.x;
    const int lane = tid & 31, warp = tid >> 5;
    const int mi = warp / 5, ni = warp % 5;
    const int s    = tid & 7;          // sample for epilogue units
    const int col0 = tid >> 3;         // 0..99; units: (col0, s) and (col0+100, s)
    const int base = blockIdx.x * SB;

    for (int i = tid; i < SB * 16; i += NTH) {
        int smp = base + (i >> 4);
        if (smp >= n) smp = n - 1;
        shz[i >> 4][i & 15] = z[smp * 16 + (i & 15)];
    }
    __syncthreads();

    float s1r[2], s2r[2];

    // ---------- phase 0: x1 = z@W0 + b0 ; seed tangents into Ab ----------
    #pragma unroll
    for (int j = 0; j < 2; j++) {
        int col = col0 + 100 * j;
        float x = b0[col];
        #pragma unroll
        for (int m = 0; m < 16; m++) x = fmaf(shz[s][m], W0[m * HID + col], x);
        float s1 = sigm(x);
        s1r[j] = s1;
        Ab[(s * 10 + 8) * RS + col] = softplusf(x);   // h1
        Ab[(s * 10 + 9) * RS + col] = 0.0f;           // pad row (stays 0 forever)
        #pragma unroll
        for (int d = 0; d < DD; d++)
            Ab[(s * 10 + d) * RS + col] = s1 * W0[(DD + d) * HID + col];   // th1
    }
    __syncthreads();

    // ---------- phase 1: W1 -> x2 + t2 ----------
    gemm_phase(0, Ab, Cb, mi, ni, lane);
    __syncthreads();
    #pragma unroll
    for (int j = 0; j < 2; j++) {
        int col = col0 + 100 * j;
        float x2 = Cb[(s * 10 + 8) * RS + col] + b1[col];
        float s2 = sigm(x2);
        s2r[j] = s2;
        float v[DD];
        #pragma unroll
        for (int d = 0; d < DD; d++) {
            v[d] = s2 * Cb[(s * 10 + d) * RS + col];   // th2 = s2*t2
            Ab[(s * 10 + d) * RS + col] = v[d];
        }
        Ab[(s * 10 + 8) * RS + col] = softplusf(x2);   // h2
        th2b[col][s][0] = bfpack(v[0], v[1]);
        th2b[col][s][1] = bfpack(v[2], v[3]);
        th2b[col][s][2] = bfpack(v[4], v[5]);
        th2b[col][s][3] = bfpack(v[6], v[7]);
    }
    __syncthreads();

    // ---------- phase 2: W2 -> x3 + t3 ----------
    gemm_phase(1, Ab, Cb, mi, ni, lane);
    __syncthreads();
    #pragma unroll
    for (int j = 0; j < 2; j++) {
        int col = col0 + 100 * j;
        float x3 = Cb[(s * 10 + 8) * RS + col] + b2[col];
        float s3 = sigm(x3);
        float w3 = W3[col];
        float c = w3 * s3 * (1.0f - s3);
        #pragma unroll
        for (int d = 0; d < DD; d++)
            Ab[(s * 10 + d) * RS + col] = c * Cb[(s * 10 + d) * RS + col];  // delta-d3
        Ab[(s * 10 + 8) * RS + col] = w3 * s3;                               // d3
    }
    __syncthreads();

    // ---------- phase 3: W2^T -> u2 + r2 ----------
    gemm_phase(2, Ab, Cb, mi, ni, lane);
    __syncthreads();
    #pragma unroll
    for (int j = 0; j < 2; j++) {
        int col = col0 + 100 * j;
        float u2 = Cb[(s * 10 + 8) * RS + col];
        float s2 = s2r[j];
        float kk = (1.0f - s2) * u2;
        float t2v[DD];
        { float2 p;
          p = bfunpack(th2b[col][s][0]); t2v[0] = p.x; t2v[1] = p.y;
          p = bfunpack(th2b[col][s][1]); t2v[2] = p.x; t2v[3] = p.y;
          p = bfunpack(th2b[col][s][2]); t2v[4] = p.x; t2v[5] = p.y;
          p = bfunpack(th2b[col][s][3]); t2v[6] = p.x; t2v[7] = p.y; }
        #pragma unroll
        for (int d = 0; d < DD; d++)
            Ab[(s * 10 + d) * RS + col] =
                fmaf(s2, Cb[(s * 10 + d) * RS + col], kk * t2v[d]);          // delta-d2
        Ab[(s * 10 + 8) * RS + col] = s2 * u2;                               // d2
    }
    __syncthreads();

    // ---------- phase 4: W1^T -> u1 + r1 ----------
    gemm_phase(3, Ab, Cb, mi, ni, lane);
    __syncthreads();
    #pragma unroll
    for (int j = 0; j < 2; j++) {
        int col = col0 + 100 * j;
        float u1 = Cb[(s * 10 + 8) * RS + col];
        float s1 = s1r[j];
        float co = s1 * (1.0f - s1) * u1;
        #pragma unroll
        for (int d = 0; d < DD; d++)
            Ab[(s * 10 + d) * RS + col] =
                fmaf(s1, Cb[(s * 10 + d) * RS + col], co * W0[(DD + d) * HID + col]);  // delta-d1
        Ab[(s * 10 + 8) * RS + col] = s1 * u1;                               // d1
    }
    __syncthreads();

    // ---------- final dots ----------
    for (int idx = warp; idx < SB * 16; idx += NWARP) {
        int ss = idx >> 4, m = idx & 15;
        float a = 0.0f;
        for (int k = lane; k < HID; k += 32)
            a = fmaf(W0[m * HID + k], Ab[(ss * 10 + 8) * RS + k], a);
        #pragma unroll
        for (int off = 16; off > 0; off >>= 1) a += __shfl_xor_sync(0xffffffffu, a, off);
        if (lane == 0) sh_g[ss][m] = a;
    }
    for (int idx = warp; idx < SB * 128; idx += NWARP) {
        int ss = idx >> 7;
        int r = idx & 127;
        int d = r >> 4, m = r & 15;
        float a = 0.0f;
        for (int k = lane; k < HID; k += 32)
            a = fmaf(W0[m * HID + k], Ab[(ss * 10 + d) * RS + k], a);
        #pragma unroll
        for (int off = 16; off > 0; off >>= 1) a += __shfl_xor_sync(0xffffffffu, a, off);
        if (lane == 0) sh_H[ss][d][m] = a;
    }
    __syncthreads();

    // ---------- per-sample 8x8 solve + output ----------
    if (tid < SB && base + tid < n) {
        const int ss = tid;
        float Mt[DD][DD], Fv[DD], av2[DD], vv[DD];
        #pragma unroll
        for (int c = 0; c < DD; c++) vv[c] = shz[ss][DD + c];
        for (int r = 0; r < DD; r++)
            for (int c = 0; c < DD; c++)
                Mt[r][c] = sh_H[ss][r][DD + c] + ((r == c) ? 2.0f * EPSV : 0.0f);
        for (int p = 0; p < DD; p++) {
            float f = sh_g[ss][p];
            for (int c = 0; c < DD; c++) f -= sh_H[ss][p][c] * vv[c];
            Fv[p] = f;
        }
        for (int col = 0; col < DD; col++) {
            int piv = col; float best = fabsf(Mt[col][col]);
            for (int r = col + 1; r < DD; r++) {
                float m = fabsf(Mt[r][col]);
                if (m > best) { best = m; piv = r; }
            }
            if (piv != col) {
                for (int c = col; c < DD; c++) { float t = Mt[col][c]; Mt[col][c] = Mt[piv][c]; Mt[piv][c] = t; }
                float t = Fv[col]; Fv[col] = Fv[piv]; Fv[piv] = t;
            }
            float inv = 1.0f / Mt[col][col];
            for (int r = col + 1; r < DD; r++) {
                float fac = Mt[r][col] * inv;
                for (int c = col; c < DD; c++) Mt[r][c] -= fac * Mt[col][c];
                Fv[r] -= fac * Fv[col];
            }
        }
        for (int r = DD - 1; r >= 0; r--) {
            float x = Fv[r];
            for (int c = r + 1; c < DD; c++) x -= Mt[r][c] * av2[c];
            av2[r] = x / Mt[r][r];
        }
        const int gi = (base + ss) * 16;
        #pragma unroll
        for (int jj = 0; jj < DD; jj++) out[gi + jj] = vv[jj];
        #pragma unroll
        for (int jj = 0; jj < DD; jj++) out[gi + DD + jj] = av2[jj];
    }
}

extern "C" void kernel_launch(void* const* d_in, const int* in_sizes, int n_in,
                              void* d_out, int out_size) {
    const float* z  = (const float*)d_in[1];
    const float* W0 = (const float*)d_in[2];
    const float* b0 = (const float*)d_in[3];
    const float* W1 = (const float*)d_in[4];
    const float* b1 = (const float*)d_in[5];
    const float* W2 = (const float*)d_in[6];
    const float* b2 = (const float*)d_in[7];
    const float* W3 = (const float*)d_in[8];
    float* out = (float*)d_out;

    const int n = in_sizes[1] / 16;

    cudaFuncSetAttribute(lnn_kernel, cudaFuncAttributeMaxDynamicSharedMemorySize, DSMEM);

    prepW<<<(HID * HID + 255) / 256, 256>>>(W1, W2);

    const int blocks = (n + SB - 1) / SB;
    lnn_kernel<<<blocks, NTH, DSMEM>>>(z, W0, b0, b1, b2, W3, out, n);
}